// round 3
// baseline (speedup 1.0000x reference)
#include <cuda_runtime.h>
#include <cuda_bf16.h>

#define N_ 32
#define C_ 3
#define H_ 224
#define W_ 224
#define S_ 17            // thetas per batch (1 zero + 16 random)
#define WPT 4            // w-positions per thread (float4 store)

#define WCHUNKS (W_ / WPT)            // 56
#define HW_CHUNKS (H_ * WCHUNKS)      // 12544
#define TOTAL_THREADS (N_ * S_ * HW_CHUNKS)   // 6,823,936

__global__ __launch_bounds__(256)
void rot_bilinear_kernel(const float* __restrict__ x,
                         const float* __restrict__ thetas,
                         float* __restrict__ out)
{
    int tid = blockIdx.x * blockDim.x + threadIdx.x;
    if (tid >= TOTAL_THREADS) return;

    // decompose: tid -> (n, s, h, w4)
    int hw = tid % HW_CHUNKS;
    int ns = tid / HW_CHUNKS;
    int w4 = hw % WCHUNKS;
    int h  = hw / WCHUNKS;
    int n  = ns / S_;

    float theta = __ldg(&thetas[ns]);
    float sn, cs;
    __sincosf(theta, &sn, &cs);

    const float inv = 2.0f / 224.0f;
    float ys = (h + 0.5f) * inv - 1.0f;

    const float* img = x + (size_t)n * (C_ * H_ * W_);
    const float* p0 = img;
    const float* p1 = img + H_ * W_;
    const float* p2 = img + 2 * H_ * W_;

    float acc0[WPT], acc1[WPT], acc2[WPT];

    int w0 = w4 * WPT;

    // initial image-space coords for w = w0; per-w step is exactly (cs, sn):
    //   ix = (cs*xs - sn*ys)*112 + 111.5, xs steps by 2/224 -> ix steps by cs
    float xs0 = (w0 + 0.5f) * inv - 1.0f;
    float ix = fmaf(cs * xs0 - sn * ys, 112.0f, 111.5f);
    float iy = fmaf(sn * xs0 + cs * ys, 112.0f, 111.5f);

#pragma unroll
    for (int wi = 0; wi < WPT; wi++) {
        float ix0f = floorf(ix);
        float iy0f = floorf(iy);
        float wx1 = ix - ix0f;
        float wy1 = iy - iy0f;
        float wx0 = 1.0f - wx1;
        float wy0 = 1.0f - wy1;

        int ix0 = (int)ix0f;
        int iy0 = (int)iy0f;
        int ix1 = ix0 + 1;
        int iy1 = iy0 + 1;

        // zero-pad: validity folded into weights (matches reference w * valid)
        float fx0 = ((unsigned)ix0 < (unsigned)W_) ? wx0 : 0.0f;
        float fx1 = ((unsigned)ix1 < (unsigned)W_) ? wx1 : 0.0f;
        float fy0 = ((unsigned)iy0 < (unsigned)H_) ? wy0 : 0.0f;
        float fy1 = ((unsigned)iy1 < (unsigned)H_) ? wy1 : 0.0f;

        float w00 = fy0 * fx0;
        float w01 = fy0 * fx1;
        float w10 = fy1 * fx0;
        float w11 = fy1 * fx1;

        // clamped indices
        int cx0 = min(max(ix0, 0), W_ - 1);
        int cx1 = min(max(ix1, 0), W_ - 1);
        int cy0 = min(max(iy0, 0), H_ - 1);
        int cy1 = min(max(iy1, 0), H_ - 1);

        int o00 = cy0 * W_ + cx0;
        int o01 = cy0 * W_ + cx1;
        int o10 = cy1 * W_ + cx0;
        int o11 = cy1 * W_ + cx1;

        // ---- issue ALL 12 gathers first (MLP batching), then FMA tree ----
        float a00 = __ldg(p0 + o00), a01 = __ldg(p0 + o01),
              a10 = __ldg(p0 + o10), a11 = __ldg(p0 + o11);
        float b00 = __ldg(p1 + o00), b01 = __ldg(p1 + o01),
              b10 = __ldg(p1 + o10), b11 = __ldg(p1 + o11);
        float c00 = __ldg(p2 + o00), c01 = __ldg(p2 + o01),
              c10 = __ldg(p2 + o10), c11 = __ldg(p2 + o11);

        float v0 = a00 * w00;
        v0 = fmaf(a01, w01, v0);
        v0 = fmaf(a10, w10, v0);
        v0 = fmaf(a11, w11, v0);
        acc0[wi] = v0;

        float v1 = b00 * w00;
        v1 = fmaf(b01, w01, v1);
        v1 = fmaf(b10, w10, v1);
        v1 = fmaf(b11, w11, v1);
        acc1[wi] = v1;

        float v2 = c00 * w00;
        v2 = fmaf(c01, w01, v2);
        v2 = fmaf(c10, w10, v2);
        v2 = fmaf(c11, w11, v2);
        acc2[wi] = v2;

        // incremental step to next w
        ix += cs;
        iy += sn;
    }

    // output layout: [n][s][c][h][w], fully coalesced float4 stores
    size_t obase = ((size_t)ns * C_) * (H_ * W_) + h * W_ + w0;
    *reinterpret_cast<float4*>(out + obase) =
        make_float4(acc0[0], acc0[1], acc0[2], acc0[3]);
    *reinterpret_cast<float4*>(out + obase + H_ * W_) =
        make_float4(acc1[0], acc1[1], acc1[2], acc1[3]);
    *reinterpret_cast<float4*>(out + obase + 2 * H_ * W_) =
        make_float4(acc2[0], acc2[1], acc2[2], acc2[3]);
}

extern "C" void kernel_launch(void* const* d_in, const int* in_sizes, int n_in,
                              void* d_out, int out_size)
{
    const float* x      = (const float*)d_in[0];
    const float* thetas = (const float*)d_in[1];
    float* out          = (float*)d_out;

    int threads = 256;
    int blocks = (TOTAL_THREADS + threads - 1) / threads;
    rot_bilinear_kernel<<<blocks, threads>>>(x, thetas, out);
}

// round 4
// speedup vs baseline: 1.8516x; 1.8516x over previous
#include <cuda_runtime.h>
#include <cuda_bf16.h>

#define N_ 32
#define C_ 3
#define H_ 224
#define W_ 224
#define S_ 17            // thetas per batch (1 zero + 16 random)
#define HPT 4            // h-rows per thread (vertical quad)

#define HQ (H_ / HPT)                 // 56 row-groups
#define THREADS W_                    // 224 = 7 warps, warp = 32 consecutive w at one h
#define NBLOCKS (N_ * S_ * HQ)        // 30464

__global__ __launch_bounds__(THREADS)
void rot_bilinear_kernel(const float* __restrict__ x,
                         const float* __restrict__ thetas,
                         float* __restrict__ out)
{
    int w  = threadIdx.x;
    int b  = blockIdx.x;
    int hq = b % HQ;
    int ns = b / HQ;
    int n  = ns / S_;

    float theta = __ldg(&thetas[ns]);
    float sn, cs;
    __sincosf(theta, &sn, &cs);

    const float inv = 2.0f / 224.0f;
    int h0 = hq * HPT;

    // image-space source coords for (h0, w); per h-step: ix -= sn, iy += cs
    float xs = (w  + 0.5f) * inv - 1.0f;
    float ys = (h0 + 0.5f) * inv - 1.0f;
    float ix = fmaf(cs * xs - sn * ys, 112.0f, 111.5f);
    float iy = fmaf(sn * xs + cs * ys, 112.0f, 111.5f);

    const float* img = x + (size_t)n * (C_ * H_ * W_);
    const float* p0 = img;
    const float* p1 = img + H_ * W_;
    const float* p2 = img + 2 * H_ * W_;

    size_t obase = (size_t)ns * (C_ * H_ * W_) + (size_t)h0 * W_ + w;

#pragma unroll
    for (int r = 0; r < HPT; r++) {
        float ix0f = floorf(ix);
        float iy0f = floorf(iy);
        float wx1 = ix - ix0f;
        float wy1 = iy - iy0f;
        float wx0 = 1.0f - wx1;
        float wy0 = 1.0f - wy1;

        int ix0 = (int)ix0f;
        int iy0 = (int)iy0f;
        int ix1 = ix0 + 1;
        int iy1 = iy0 + 1;

        // zero-pad: validity folded into weights (matches reference w * valid)
        float fx0 = ((unsigned)ix0 < (unsigned)W_) ? wx0 : 0.0f;
        float fx1 = ((unsigned)ix1 < (unsigned)W_) ? wx1 : 0.0f;
        float fy0 = ((unsigned)iy0 < (unsigned)H_) ? wy0 : 0.0f;
        float fy1 = ((unsigned)iy1 < (unsigned)H_) ? wy1 : 0.0f;

        float w00 = fy0 * fx0;
        float w01 = fy0 * fx1;
        float w10 = fy1 * fx0;
        float w11 = fy1 * fx1;

        // clamped indices
        int cx0 = min(max(ix0, 0), W_ - 1);
        int cx1 = min(max(ix1, 0), W_ - 1);
        int cy0 = min(max(iy0, 0), H_ - 1);
        int cy1 = min(max(iy1, 0), H_ - 1);

        int o00 = cy0 * W_ + cx0;
        int o01 = cy0 * W_ + cx1;
        int o10 = cy1 * W_ + cx0;
        int o11 = cy1 * W_ + cx1;

        // ---- issue ALL 12 gathers first (MLP batching), then FMA trees ----
        float a00 = __ldg(p0 + o00), a01 = __ldg(p0 + o01),
              a10 = __ldg(p0 + o10), a11 = __ldg(p0 + o11);
        float b00 = __ldg(p1 + o00), b01 = __ldg(p1 + o01),
              b10 = __ldg(p1 + o10), b11 = __ldg(p1 + o11);
        float c00 = __ldg(p2 + o00), c01 = __ldg(p2 + o01),
              c10 = __ldg(p2 + o10), c11 = __ldg(p2 + o11);

        float v0 = a00 * w00;
        v0 = fmaf(a01, w01, v0);
        v0 = fmaf(a10, w10, v0);
        v0 = fmaf(a11, w11, v0);

        float v1 = b00 * w00;
        v1 = fmaf(b01, w01, v1);
        v1 = fmaf(b10, w10, v1);
        v1 = fmaf(b11, w11, v1);

        float v2 = c00 * w00;
        v2 = fmaf(c01, w01, v2);
        v2 = fmaf(c10, w10, v2);
        v2 = fmaf(c11, w11, v2);

        // coalesced row stores: warp writes one full 128B line per STG
        out[obase + (size_t)r * W_]                 = v0;
        out[obase + (size_t)r * W_ + H_ * W_]       = v1;
        out[obase + (size_t)r * W_ + 2 * H_ * W_]   = v2;

        // incremental step to next output row
        ix -= sn;
        iy += cs;
    }
}

extern "C" void kernel_launch(void* const* d_in, const int* in_sizes, int n_in,
                              void* d_out, int out_size)
{
    const float* x      = (const float*)d_in[0];
    const float* thetas = (const float*)d_in[1];
    float* out          = (float*)d_out;

    rot_bilinear_kernel<<<NBLOCKS, THREADS>>>(x, thetas, out);
}

// round 6
// speedup vs baseline: 2.3479x; 1.2680x over previous
#include <cuda_runtime.h>
#include <cuda_bf16.h>

#define N_ 32
#define C_ 3
#define H_ 224
#define W_ 224
#define S_ 17            // thetas per batch (1 zero + 16 random)
#define HPT 4            // h-rows per thread (vertical quad)

#define HQ (H_ / HPT)                 // 56 row-groups
#define THREADS W_                    // 224 = 7 warps; warp = 32 consecutive w at one h
#define NBLOCKS (N_ * S_ * HQ)        // 30464

#define NPIX (N_ * H_ * W_)           // 1,605,632 pixels

// channel-packed scratch: quad[n*H*W + y*W + x] = (c0, c1, c2, 0)
__device__ float4 g_quad[NPIX];

// Each thread packs 4 consecutive pixels: reads 3x float4 (one per channel),
// writes 4x float4. H*W = 50176 divisible by 4, planes are 16B-aligned.
__global__ __launch_bounds__(256)
void pack_kernel(const float* __restrict__ x)
{
    int i4 = blockIdx.x * blockDim.x + threadIdx.x;   // pixel-quad index
    if (i4 >= NPIX / 4) return;
    int i  = i4 * 4;
    int n  = i / (H_ * W_);
    int yx = i - n * (H_ * W_);
    const float* img = x + (size_t)n * (C_ * H_ * W_) + yx;
    float4 c0 = *reinterpret_cast<const float4*>(img);
    float4 c1 = *reinterpret_cast<const float4*>(img + H_ * W_);
    float4 c2 = *reinterpret_cast<const float4*>(img + 2 * H_ * W_);
    g_quad[i + 0] = make_float4(c0.x, c1.x, c2.x, 0.0f);
    g_quad[i + 1] = make_float4(c0.y, c1.y, c2.y, 0.0f);
    g_quad[i + 2] = make_float4(c0.z, c1.z, c2.z, 0.0f);
    g_quad[i + 3] = make_float4(c0.w, c1.w, c2.w, 0.0f);
}

__global__ __launch_bounds__(THREADS)
void rot_bilinear_kernel(const float* __restrict__ thetas,
                         float* __restrict__ out)
{
    int w  = threadIdx.x;
    int b  = blockIdx.x;
    int hq = b % HQ;
    int ns = b / HQ;
    int n  = ns / S_;

    float theta = __ldg(&thetas[ns]);
    float sn, cs;
    __sincosf(theta, &sn, &cs);

    const float inv = 2.0f / 224.0f;
    int h0 = hq * HPT;

    // image-space source coords for (h0, w); per h-step: ix -= sn, iy += cs
    float xs = (w  + 0.5f) * inv - 1.0f;
    float ys = (h0 + 0.5f) * inv - 1.0f;
    float ix = fmaf(cs * xs - sn * ys, 112.0f, 111.5f);
    float iy = fmaf(sn * xs + cs * ys, 112.0f, 111.5f);

    const float4* quad = g_quad + (size_t)n * (H_ * W_);

    size_t obase = (size_t)ns * (C_ * H_ * W_) + (size_t)h0 * W_ + w;

#pragma unroll
    for (int r = 0; r < HPT; r++) {
        float ix0f = floorf(ix);
        float iy0f = floorf(iy);
        float wx1 = ix - ix0f;
        float wy1 = iy - iy0f;
        float wx0 = 1.0f - wx1;
        float wy0 = 1.0f - wy1;

        int ix0 = (int)ix0f;
        int iy0 = (int)iy0f;
        int ix1 = ix0 + 1;
        int iy1 = iy0 + 1;

        // zero-pad: validity folded into weights (matches reference w * valid)
        float fx0 = ((unsigned)ix0 < (unsigned)W_) ? wx0 : 0.0f;
        float fx1 = ((unsigned)ix1 < (unsigned)W_) ? wx1 : 0.0f;
        float fy0 = ((unsigned)iy0 < (unsigned)H_) ? wy0 : 0.0f;
        float fy1 = ((unsigned)iy1 < (unsigned)H_) ? wy1 : 0.0f;

        float w00 = fy0 * fx0;
        float w01 = fy0 * fx1;
        float w10 = fy1 * fx0;
        float w11 = fy1 * fx1;

        // clamped indices
        int cx0 = min(max(ix0, 0), W_ - 1);
        int cx1 = min(max(ix1, 0), W_ - 1);
        int cy0 = min(max(iy0, 0), H_ - 1);
        int cy1 = min(max(iy1, 0), H_ - 1);

        // 4 channel-packed corner gathers (LDG.128 each, all 3 channels at once)
        float4 q00 = __ldg(quad + (cy0 * W_ + cx0));
        float4 q01 = __ldg(quad + (cy0 * W_ + cx1));
        float4 q10 = __ldg(quad + (cy1 * W_ + cx0));
        float4 q11 = __ldg(quad + (cy1 * W_ + cx1));

        float v0 = q00.x * w00;
        v0 = fmaf(q01.x, w01, v0);
        v0 = fmaf(q10.x, w10, v0);
        v0 = fmaf(q11.x, w11, v0);

        float v1 = q00.y * w00;
        v1 = fmaf(q01.y, w01, v1);
        v1 = fmaf(q10.y, w10, v1);
        v1 = fmaf(q11.y, w11, v1);

        float v2 = q00.z * w00;
        v2 = fmaf(q01.z, w01, v2);
        v2 = fmaf(q10.z, w10, v2);
        v2 = fmaf(q11.z, w11, v2);

        // coalesced row stores: warp writes one full 128B line per STG
        out[obase + (size_t)r * W_]                 = v0;
        out[obase + (size_t)r * W_ + H_ * W_]       = v1;
        out[obase + (size_t)r * W_ + 2 * H_ * W_]   = v2;

        // incremental step to next output row
        ix -= sn;
        iy += cs;
    }
}

extern "C" void kernel_launch(void* const* d_in, const int* in_sizes, int n_in,
                              void* d_out, int out_size)
{
    const float* x      = (const float*)d_in[0];
    const float* thetas = (const float*)d_in[1];
    float* out          = (float*)d_out;

    pack_kernel<<<(NPIX / 4 + 255) / 256, 256>>>(x);
    rot_bilinear_kernel<<<NBLOCKS, THREADS>>>(thetas, out);
}

// round 9
// speedup vs baseline: 3.0934x; 1.3175x over previous
#include <cuda_runtime.h>
#include <cuda_fp16.h>

#define N_ 32
#define C_ 3
#define H_ 224
#define W_ 224
#define S_ 17            // thetas per batch (1 zero + 16 random)
#define HPT 4            // h-rows per thread (vertical quad)

#define HQ (H_ / HPT)                 // 56 row-groups
#define THREADS W_                    // 224 = 7 warps; warp = 32 consecutive w at one h
#define NBLOCKS (N_ * S_ * HQ)        // 30464

#define NPIX (N_ * H_ * W_)           // 1,605,632 pixels

// fp16 channel-packed scratch: 8 B/pixel = (h0,h1 | h2,pad)
__device__ uint2 g_quad[NPIX];

static __device__ __forceinline__ unsigned h2_as_u(__half2 h)
{
    return *reinterpret_cast<unsigned*>(&h);
}

// Each thread packs 4 consecutive pixels: reads 3x float4, writes 4x uint2.
__global__ __launch_bounds__(256)
void pack_kernel(const float* __restrict__ x)
{
    int i4 = blockIdx.x * blockDim.x + threadIdx.x;   // pixel-quad index
    if (i4 >= NPIX / 4) return;
    int i  = i4 * 4;
    int n  = i / (H_ * W_);
    int yx = i - n * (H_ * W_);
    const float* img = x + (size_t)n * (C_ * H_ * W_) + yx;
    float4 c0 = *reinterpret_cast<const float4*>(img);
    float4 c1 = *reinterpret_cast<const float4*>(img + H_ * W_);
    float4 c2 = *reinterpret_cast<const float4*>(img + 2 * H_ * W_);

    g_quad[i + 0] = make_uint2(h2_as_u(__floats2half2_rn(c0.x, c1.x)),
                               h2_as_u(__floats2half2_rn(c2.x, 0.0f)));
    g_quad[i + 1] = make_uint2(h2_as_u(__floats2half2_rn(c0.y, c1.y)),
                               h2_as_u(__floats2half2_rn(c2.y, 0.0f)));
    g_quad[i + 2] = make_uint2(h2_as_u(__floats2half2_rn(c0.z, c1.z)),
                               h2_as_u(__floats2half2_rn(c2.z, 0.0f)));
    g_quad[i + 3] = make_uint2(h2_as_u(__floats2half2_rn(c0.w, c1.w)),
                               h2_as_u(__floats2half2_rn(c2.w, 0.0f)));
}

static __device__ __forceinline__ void unpack3(uint2 raw, float& a, float& b, float& c)
{
    __half2 h01 = *reinterpret_cast<__half2*>(&raw.x);
    __half2 h2p = *reinterpret_cast<__half2*>(&raw.y);
    float2 f01 = __half22float2(h01);
    a = f01.x;
    b = f01.y;
    c = __low2float(h2p);
}

__global__ __launch_bounds__(THREADS)
void rot_bilinear_kernel(const float* __restrict__ thetas,
                         float* __restrict__ out)
{
    int w  = threadIdx.x;
    int b  = blockIdx.x;
    int hq = b % HQ;
    int ns = b / HQ;
    int n  = ns / S_;

    float theta = __ldg(&thetas[ns]);
    float sn, cs;
    __sincosf(theta, &sn, &cs);

    const float inv = 2.0f / 224.0f;
    int h0 = hq * HPT;

    // image-space source coords for (h0, w); per h-step: ix -= sn, iy += cs
    float xs = (w  + 0.5f) * inv - 1.0f;
    float ys = (h0 + 0.5f) * inv - 1.0f;
    float ix = fmaf(cs * xs - sn * ys, 112.0f, 111.5f);
    float iy = fmaf(sn * xs + cs * ys, 112.0f, 111.5f);

    const uint2* quad = g_quad + (size_t)n * (H_ * W_);

    size_t obase = (size_t)ns * (C_ * H_ * W_) + (size_t)h0 * W_ + w;

#pragma unroll
    for (int r = 0; r < HPT; r++) {
        float ix0f = floorf(ix);
        float iy0f = floorf(iy);
        float wx1 = ix - ix0f;
        float wy1 = iy - iy0f;
        float wx0 = 1.0f - wx1;
        float wy0 = 1.0f - wy1;

        int ix0 = (int)ix0f;
        int iy0 = (int)iy0f;
        int ix1 = ix0 + 1;
        int iy1 = iy0 + 1;

        // zero-pad: validity folded into weights (matches reference w * valid)
        float fx0 = ((unsigned)ix0 < (unsigned)W_) ? wx0 : 0.0f;
        float fx1 = ((unsigned)ix1 < (unsigned)W_) ? wx1 : 0.0f;
        float fy0 = ((unsigned)iy0 < (unsigned)H_) ? wy0 : 0.0f;
        float fy1 = ((unsigned)iy1 < (unsigned)H_) ? wy1 : 0.0f;

        float w00 = fy0 * fx0;
        float w01 = fy0 * fx1;
        float w10 = fy1 * fx0;
        float w11 = fy1 * fx1;

        // clamped indices
        int cx0 = min(max(ix0, 0), W_ - 1);
        int cx1 = min(max(ix1, 0), W_ - 1);
        int cy0 = min(max(iy0, 0), H_ - 1);
        int cy1 = min(max(iy1, 0), H_ - 1);

        // 4 fp16 channel-packed corner gathers (LDG.64 each)
        uint2 r00 = __ldg(quad + (cy0 * W_ + cx0));
        uint2 r01 = __ldg(quad + (cy0 * W_ + cx1));
        uint2 r10 = __ldg(quad + (cy1 * W_ + cx0));
        uint2 r11 = __ldg(quad + (cy1 * W_ + cx1));

        float a00, b00, c00;  unpack3(r00, a00, b00, c00);
        float a01, b01, c01;  unpack3(r01, a01, b01, c01);
        float a10, b10, c10;  unpack3(r10, a10, b10, c10);
        float a11, b11, c11;  unpack3(r11, a11, b11, c11);

        float v0 = a00 * w00;
        v0 = fmaf(a01, w01, v0);
        v0 = fmaf(a10, w10, v0);
        v0 = fmaf(a11, w11, v0);

        float v1 = b00 * w00;
        v1 = fmaf(b01, w01, v1);
        v1 = fmaf(b10, w10, v1);
        v1 = fmaf(b11, w11, v1);

        float v2 = c00 * w00;
        v2 = fmaf(c01, w01, v2);
        v2 = fmaf(c10, w10, v2);
        v2 = fmaf(c11, w11, v2);

        // coalesced row stores: warp writes one full 128B line per STG
        out[obase + (size_t)r * W_]                 = v0;
        out[obase + (size_t)r * W_ + H_ * W_]       = v1;
        out[obase + (size_t)r * W_ + 2 * H_ * W_]   = v2;

        // incremental step to next output row
        ix -= sn;
        iy += cs;
    }
}

extern "C" void kernel_launch(void* const* d_in, const int* in_sizes, int n_in,
                              void* d_out, int out_size)
{
    const float* x      = (const float*)d_in[0];
    const float* thetas = (const float*)d_in[1];
    float* out          = (float*)d_out;

    pack_kernel<<<(NPIX / 4 + 255) / 256, 256>>>(x);
    rot_bilinear_kernel<<<NBLOCKS, THREADS>>>(thetas, out);
}

// round 11
// speedup vs baseline: 3.1584x; 1.0210x over previous
#include <cuda_runtime.h>
#include <cuda_fp16.h>

#define N_ 32
#define C_ 3
#define H_ 224
#define W_ 224
#define S_ 17            // thetas per batch
#define HPT 4            // h-rows per thread

#define HQ (H_ / HPT)                 // 56 row-groups
#define THREADS W_                    // 224 = 7 warps; warp = 32 consecutive w at one h
#define NBLOCKS (N_ * S_ * HQ)        // 30464

// padded pair grid: x,y in [-2, 225] -> 228 x 228 entries
#define PW 228
#define PH 228
#define NPAIR (N_ * PH * PW)          // 1,663,488 entries * 16 B = 26.6 MB

// g_pair[n][py][px] = uint4{ h2(c0_x,c0_x1), h2(c1_x,c1_x1), h2(c2_x,c2_x1), 0 }
// where x = px-2, pair covers image pixels (x, x+1); OOB pixels stored as 0.
__device__ uint4 g_pair[NPAIR];

static __device__ __forceinline__ unsigned h2u(float a, float b)
{
    __half2 h = __floats2half2_rn(a, b);   // .x = a (lo), .y = b (hi)
    return *reinterpret_cast<unsigned*>(&h);
}

static __device__ __forceinline__ float2 u2f(unsigned u)
{
    __half2 h = *reinterpret_cast<__half2*>(&u);
    return __half22float2(h);              // .x = lo, .y = hi
}

__global__ __launch_bounds__(256)
void pack_kernel(const float* __restrict__ x)
{
    int e = blockIdx.x * blockDim.x + threadIdx.x;
    if (e >= NPAIR) return;
    int n   = e / (PH * PW);
    int rem = e - n * (PH * PW);
    int py  = rem / PW;
    int px  = rem - py * PW;
    int y   = py - 2;
    int x0  = px - 2;
    int x1  = x0 + 1;

    float c0a = 0.f, c1a = 0.f, c2a = 0.f;
    float c0b = 0.f, c1b = 0.f, c2b = 0.f;
    if ((unsigned)y < (unsigned)H_) {
        const float* img = x + (size_t)n * (C_ * H_ * W_) + (size_t)y * W_;
        if ((unsigned)x0 < (unsigned)W_) {
            c0a = img[x0];
            c1a = img[x0 + H_ * W_];
            c2a = img[x0 + 2 * H_ * W_];
        }
        if ((unsigned)x1 < (unsigned)W_) {
            c0b = img[x1];
            c1b = img[x1 + H_ * W_];
            c2b = img[x1 + 2 * H_ * W_];
        }
    }
    uint4 q;
    q.x = h2u(c0a, c0b);
    q.y = h2u(c1a, c1b);
    q.z = h2u(c2a, c2b);
    q.w = 0u;
    g_pair[e] = q;
}

__global__ __launch_bounds__(THREADS)
void rot_bilinear_kernel(const float* __restrict__ thetas,
                         float* __restrict__ out)
{
    int w  = threadIdx.x;
    int b  = blockIdx.x;
    int hq = b % HQ;
    int ns = b / HQ;
    int n  = ns / S_;

    float theta = __ldg(&thetas[ns]);
    float sn, cs;
    __sincosf(theta, &sn, &cs);

    const float inv = 2.0f / 224.0f;
    int h0 = hq * HPT;

    // image-space source coords for (h0, w); per h-step: ix -= sn, iy += cs
    float xs = (w  + 0.5f) * inv - 1.0f;
    float ys = (h0 + 0.5f) * inv - 1.0f;
    float ix = fmaf(cs * xs - sn * ys, 112.0f, 111.5f);
    float iy = fmaf(sn * xs + cs * ys, 112.0f, 111.5f);

    const uint4* pair = g_pair + (size_t)n * (PH * PW);

    size_t obase = (size_t)ns * (C_ * H_ * W_) + (size_t)h0 * W_ + w;

#pragma unroll
    for (int r = 0; r < HPT; r++) {
        int ix0 = __float2int_rd(ix);
        int iy0 = __float2int_rd(iy);
        float wx1 = ix - (float)ix0;
        float wy1 = iy - (float)iy0;
        float wx0 = 1.0f - wx1;
        float wy0 = 1.0f - wy1;

        float w00 = wy0 * wx0;
        float w01 = wy0 * wx1;
        float w10 = wy1 * wx0;
        float w11 = wy1 * wx1;

        // clamp into padded apron: fully-OOB pixels land on zero entries,
        // so no validity masking is needed anywhere.
        int cx = min(max(ix0, -2), 224);
        int cy = min(max(iy0, -2), 224);

        int off = (cy + 2) * PW + (cx + 2);
        uint4 A = __ldg(pair + off);        // row iy0: both x-corners, 3 ch
        uint4 B = __ldg(pair + off + PW);   // row iy0+1

        float2 a0 = u2f(A.x), a1 = u2f(A.y), a2 = u2f(A.z);
        float2 b0 = u2f(B.x), b1 = u2f(B.y), b2 = u2f(B.z);

        float v0 = a0.x * w00;
        v0 = fmaf(a0.y, w01, v0);
        v0 = fmaf(b0.x, w10, v0);
        v0 = fmaf(b0.y, w11, v0);

        float v1 = a1.x * w00;
        v1 = fmaf(a1.y, w01, v1);
        v1 = fmaf(b1.x, w10, v1);
        v1 = fmaf(b1.y, w11, v1);

        float v2 = a2.x * w00;
        v2 = fmaf(a2.y, w01, v2);
        v2 = fmaf(b2.x, w10, v2);
        v2 = fmaf(b2.y, w11, v2);

        // coalesced row stores: warp writes one full 128B line per STG
        out[obase + (size_t)r * W_]                 = v0;
        out[obase + (size_t)r * W_ + H_ * W_]       = v1;
        out[obase + (size_t)r * W_ + 2 * H_ * W_]   = v2;

        ix -= sn;
        iy += cs;
    }
}

extern "C" void kernel_launch(void* const* d_in, const int* in_sizes, int n_in,
                              void* d_out, int out_size)
{
    const float* x      = (const float*)d_in[0];
    const float* thetas = (const float*)d_in[1];
    float* out          = (float*)d_out;

    pack_kernel<<<(NPAIR + 255) / 256, 256>>>(x);
    rot_bilinear_kernel<<<NBLOCKS, THREADS>>>(thetas, out);
}

// round 14
// speedup vs baseline: 3.5227x; 1.1153x over previous
#include <cuda_runtime.h>
#include <cuda_fp16.h>

#define N_ 32
#define C_ 3
#define H_ 224
#define W_ 224
#define S_ 17            // thetas per batch
#define HPT 8            // h-rows per thread (vertical chain, enables corner reuse)

#define HQ (H_ / HPT)                 // 28 row-groups
#define THREADS W_                    // 224 = 7 warps; warp = 32 consecutive w at one h
#define NBLOCKS (N_ * S_ * HQ)        // 15232

// padded pair grid: x,y in [-2, 225] -> 228 x 228 entries
#define PW 228
#define PH 228
#define NPAIR (N_ * PH * PW)          // 26.6 MB

// g_pair[n][py][px] = uint4{ h2(c0_x,c0_x1), h2(c1_x,c1_x1), h2(c2_x,c2_x1), 0 }
// where x = px-2; OOB pixels stored as 0.
__device__ uint4 g_pair[NPAIR];

static __device__ __forceinline__ unsigned h2u(float a, float b)
{
    __half2 h = __floats2half2_rn(a, b);
    return *reinterpret_cast<unsigned*>(&h);
}

static __device__ __forceinline__ float2 u2f(unsigned u)
{
    __half2 h = *reinterpret_cast<__half2*>(&u);
    return __half22float2(h);
}

__global__ __launch_bounds__(256)
void pack_kernel(const float* __restrict__ x)
{
    int e = blockIdx.x * blockDim.x + threadIdx.x;
    if (e >= NPAIR) return;
    int n   = e / (PH * PW);
    int rem = e - n * (PH * PW);
    int py  = rem / PW;
    int px  = rem - py * PW;
    int y   = py - 2;
    int x0  = px - 2;
    int x1  = x0 + 1;

    float c0a = 0.f, c1a = 0.f, c2a = 0.f;
    float c0b = 0.f, c1b = 0.f, c2b = 0.f;
    if ((unsigned)y < (unsigned)H_) {
        const float* img = x + (size_t)n * (C_ * H_ * W_) + (size_t)y * W_;
        if ((unsigned)x0 < (unsigned)W_) {
            c0a = img[x0];
            c1a = img[x0 + H_ * W_];
            c2a = img[x0 + 2 * H_ * W_];
        }
        if ((unsigned)x1 < (unsigned)W_) {
            c0b = img[x1];
            c1b = img[x1 + H_ * W_];
            c2b = img[x1 + 2 * H_ * W_];
        }
    }
    uint4 q;
    q.x = h2u(c0a, c0b);
    q.y = h2u(c1a, c1b);
    q.z = h2u(c2a, c2b);
    q.w = 0u;
    g_pair[e] = q;
}

__global__ __launch_bounds__(THREADS)
void rot_bilinear_kernel(const float* __restrict__ thetas,
                         float* __restrict__ out)
{
    int w  = threadIdx.x;
    int b  = blockIdx.x;
    int hq = b % HQ;
    int ns = b / HQ;
    int n  = ns / S_;

    float theta = __ldg(&thetas[ns]);
    float sn, cs;
    __sincosf(theta, &sn, &cs);

    const float inv = 2.0f / 224.0f;
    int h0 = hq * HPT;

    // image-space source coords for (h0, w); per h-step: ix -= sn, iy += cs
    float xs = (w  + 0.5f) * inv - 1.0f;
    float ys = (h0 + 0.5f) * inv - 1.0f;
    float ix = fmaf(cs * xs - sn * ys, 112.0f, 111.5f);
    float iy = fmaf(sn * xs + cs * ys, 112.0f, 111.5f);

    const uint4* pair = g_pair + (size_t)n * (PH * PW);

    size_t obase = (size_t)ns * (C_ * H_ * W_) + (size_t)h0 * W_ + w;

    // corner-row cache: A = row iy0 pair, B = row iy0+1 pair
    uint4 A = make_uint4(0, 0, 0, 0);
    uint4 B = make_uint4(0, 0, 0, 0);
    int pcx = -1000000, pcy = -1000000;

#pragma unroll
    for (int r = 0; r < HPT; r++) {
        int ix0 = __float2int_rd(ix);
        int iy0 = __float2int_rd(iy);
        float wx1 = ix - (float)ix0;
        float wy1 = iy - (float)iy0;
        float wx0 = 1.0f - wx1;
        float wy0 = 1.0f - wy1;

        float w00 = wy0 * wx0;
        float w01 = wy0 * wx1;
        float w10 = wy1 * wx0;
        float w11 = wy1 * wx1;

        // clamp into padded apron (fully-OOB pixels read zero entries)
        int cx = min(max(ix0, -2), 224);
        int cy = min(max(iy0, -2), 224);

        int off = (cy + 2) * PW + (cx + 2);

        bool sx  = (cx == pcx);
        bool sy  = sx & (cy == pcy);       // both rows cached
        bool dy1 = sx & (cy == pcy + 1);   // A' = old B

        // select / predicated reload (ptxas predicates tiny ifs)
        uint4 An = dy1 ? B : A;
        uint4 Bn = B;
        bool needA = !(sy | dy1);
        bool needB = !sy;
        if (needA) An = __ldg(pair + off);
        if (needB) Bn = __ldg(pair + off + PW);
        A = An;
        B = Bn;
        pcx = cx;
        pcy = cy;

        float2 a0 = u2f(A.x), a1 = u2f(A.y), a2 = u2f(A.z);
        float2 b0 = u2f(B.x), b1 = u2f(B.y), b2 = u2f(B.z);

        float v0 = a0.x * w00;
        v0 = fmaf(a0.y, w01, v0);
        v0 = fmaf(b0.x, w10, v0);
        v0 = fmaf(b0.y, w11, v0);

        float v1 = a1.x * w00;
        v1 = fmaf(a1.y, w01, v1);
        v1 = fmaf(b1.x, w10, v1);
        v1 = fmaf(b1.y, w11, v1);

        float v2 = a2.x * w00;
        v2 = fmaf(a2.y, w01, v2);
        v2 = fmaf(b2.x, w10, v2);
        v2 = fmaf(b2.y, w11, v2);

        // coalesced row stores: warp writes one full 128B line per STG
        out[obase + (size_t)r * W_]                 = v0;
        out[obase + (size_t)r * W_ + H_ * W_]       = v1;
        out[obase + (size_t)r * W_ + 2 * H_ * W_]   = v2;

        ix -= sn;
        iy += cs;
    }
}

extern "C" void kernel_launch(void* const* d_in, const int* in_sizes, int n_in,
                              void* d_out, int out_size)
{
    const float* x      = (const float*)d_in[0];
    const float* thetas = (const float*)d_in[1];
    float* out          = (float*)d_out;

    pack_kernel<<<(NPAIR + 255) / 256, 256>>>(x);
    rot_bilinear_kernel<<<NBLOCKS, THREADS>>>(thetas, out);
}